// round 1
// baseline (speedup 1.0000x reference)
#include <cuda_runtime.h>
#include <math.h>

#define N_TOK 2048
#define HDIM  512
#define C1    256
#define D2    1024
#define KDIM  256
#define HALFD 128
#define HEADS 4
#define SUBN  512
#define KNN   32

// ---------------- static device scratch (no allocations allowed) ----------------
__device__ float g_h[N_TOK * C1];              // 2 MB
__device__ float g_q[N_TOK * D2];              // 8 MB
__device__ float g_bnpart[128 * 2 * KDIM];     // partial BN sums
__device__ float g_scale[KDIM];
__device__ float g_shift[KDIM];
__device__ float g_s[8u * N_TOK * SUBN];       // 32 MB scores [h*2+p][t][k]
__device__ int   g_idx[N_TOK * HEADS * KNN];   // selected memory rows
__device__ float g_w[N_TOK * HEADS * KNN];     // softmax weights
__device__ float g_partial[N_TOK * HDIM];      // per-token gather result

// pair-sum pruning tables: (i+1)*(j+1) <= 32  -> 119 candidates
__constant__ int c_jm[32]   = {32,16,10,8,6,5,4,4,3,3,2,2,2,2,2,2,
                               1,1,1,1,1,1,1,1,1,1,1,1,1,1,1,1};
__constant__ int c_base[32] = {0,32,48,58,66,72,77,81,85,88,91,93,95,97,99,101,
                               103,104,105,106,107,108,109,110,111,112,113,114,115,116,117,118};

__device__ __forceinline__ float neg_inf() { return __int_as_float(0xff800000u); }

// ---------------- generic tiled fp32 GEMM: C = act(A[MxK] @ B[NxK]^T + bias) ----------------
template<bool RELU>
__global__ void __launch_bounds__(256) gemm_bias(const float* __restrict__ A,
                                                 const float* __restrict__ B,
                                                 const float* __restrict__ bias,
                                                 float* __restrict__ C,
                                                 int M, int N, int K)
{
    __shared__ float As[16][64];
    __shared__ float Bs[16][64];
    const int tid = threadIdx.x;
    const int bm = blockIdx.x * 64, bn = blockIdx.y * 64;
    const int lr = tid >> 2;           // 0..63 row within tile
    const int lc = (tid & 3) << 2;     // 0,4,8,12 k-offset
    const int tx = tid & 15, ty = tid >> 4;
    float acc[4][4] = {};

    for (int k0 = 0; k0 < K; k0 += 16) {
        float4 av = *(const float4*)(A + (size_t)(bm + lr) * K + k0 + lc);
        float4 bv = *(const float4*)(B + (size_t)(bn + lr) * K + k0 + lc);
        As[lc + 0][lr] = av.x; As[lc + 1][lr] = av.y; As[lc + 2][lr] = av.z; As[lc + 3][lr] = av.w;
        Bs[lc + 0][lr] = bv.x; Bs[lc + 1][lr] = bv.y; Bs[lc + 2][lr] = bv.z; Bs[lc + 3][lr] = bv.w;
        __syncthreads();
#pragma unroll
        for (int k = 0; k < 16; k++) {
            float4 a = *(const float4*)&As[k][ty << 2];
            float4 b = *(const float4*)&Bs[k][tx << 2];
            acc[0][0] += a.x * b.x; acc[0][1] += a.x * b.y; acc[0][2] += a.x * b.z; acc[0][3] += a.x * b.w;
            acc[1][0] += a.y * b.x; acc[1][1] += a.y * b.y; acc[1][2] += a.y * b.z; acc[1][3] += a.y * b.w;
            acc[2][0] += a.z * b.x; acc[2][1] += a.z * b.y; acc[2][2] += a.z * b.z; acc[2][3] += a.z * b.w;
            acc[3][0] += a.w * b.x; acc[3][1] += a.w * b.y; acc[3][2] += a.w * b.z; acc[3][3] += a.w * b.w;
        }
        __syncthreads();
    }
    const int colb = bn + (tx << 2);
    float4 bia = *(const float4*)(bias + colb);
#pragma unroll
    for (int i = 0; i < 4; i++) {
        int row = bm + (ty << 2) + i;
        float4 o;
        o.x = acc[i][0] + bia.x; o.y = acc[i][1] + bia.y;
        o.z = acc[i][2] + bia.z; o.w = acc[i][3] + bia.w;
        if (RELU) {
            o.x = fmaxf(o.x, 0.f); o.y = fmaxf(o.y, 0.f);
            o.z = fmaxf(o.z, 0.f); o.w = fmaxf(o.w, 0.f);
        }
        *(float4*)(C + (size_t)row * N + colb) = o;
    }
}

// ---------------- BN statistics ----------------
__global__ void __launch_bounds__(256) bn_partial()
{
    // row r = t*4+h lives at g_q + r*256; block b handles 64 rows
    const int b = blockIdx.x, tid = threadIdx.x;
    const float* base = g_q + (size_t)b * 64 * KDIM;
    float s = 0.f, s2 = 0.f;
#pragma unroll 4
    for (int r = 0; r < 64; r++) {
        float v = base[r * KDIM + tid];
        s += v; s2 += v * v;
    }
    g_bnpart[(b * 2 + 0) * KDIM + tid] = s;
    g_bnpart[(b * 2 + 1) * KDIM + tid] = s2;
}

__global__ void __launch_bounds__(256) bn_finalize(const float* __restrict__ gamma,
                                                   const float* __restrict__ beta)
{
    const int d = threadIdx.x;
    float s = 0.f, s2 = 0.f;
    for (int b = 0; b < 128; b++) {
        s  += g_bnpart[(b * 2 + 0) * KDIM + d];
        s2 += g_bnpart[(b * 2 + 1) * KDIM + d];
    }
    const float inv = 1.0f / 8192.0f;
    float mean = s * inv;
    float var  = s2 * inv - mean * mean;
    float sc = rsqrtf(var + 1e-5f) * gamma[d];
    g_scale[d] = sc;
    g_shift[d] = beta[d] - mean * sc;
}

// ---------------- score GEMM with fused BN normalize ----------------
// S[z][t][k] = qn(t, head z>>1, half z&1, :) . keys[z][k][:]
__global__ void __launch_bounds__(256) score_gemm(const float* __restrict__ keys)
{
    __shared__ float As[16][64];
    __shared__ float Bs[16][64];
    const int tid = threadIdx.x;
    const int bm = blockIdx.x * 64, bn = blockIdx.y * 64;
    const int z  = blockIdx.z;               // h*2+p
    const int h  = z >> 1, p = z & 1;
    const int lr = tid >> 2;
    const int lc = (tid & 3) << 2;
    const int tx = tid & 15, ty = tid >> 4;

    const float* Bk = keys + (size_t)z * SUBN * HALFD;
    float acc[4][4] = {};

    for (int k0 = 0; k0 < HALFD; k0 += 16) {
        const int dk = p * HALFD + k0 + lc;  // index into KDIM params
        float4 av = *(const float4*)(g_q + (size_t)(bm + lr) * D2 + h * KDIM + p * HALFD + k0 + lc);
        float4 sc = *(const float4*)(g_scale + dk);
        float4 sh = *(const float4*)(g_shift + dk);
        av.x = av.x * sc.x + sh.x; av.y = av.y * sc.y + sh.y;
        av.z = av.z * sc.z + sh.z; av.w = av.w * sc.w + sh.w;
        float4 bv = *(const float4*)(Bk + (size_t)(bn + lr) * HALFD + k0 + lc);
        As[lc + 0][lr] = av.x; As[lc + 1][lr] = av.y; As[lc + 2][lr] = av.z; As[lc + 3][lr] = av.w;
        Bs[lc + 0][lr] = bv.x; Bs[lc + 1][lr] = bv.y; Bs[lc + 2][lr] = bv.z; Bs[lc + 3][lr] = bv.w;
        __syncthreads();
#pragma unroll
        for (int k = 0; k < 16; k++) {
            float4 a = *(const float4*)&As[k][ty << 2];
            float4 b = *(const float4*)&Bs[k][tx << 2];
            acc[0][0] += a.x * b.x; acc[0][1] += a.x * b.y; acc[0][2] += a.x * b.z; acc[0][3] += a.x * b.w;
            acc[1][0] += a.y * b.x; acc[1][1] += a.y * b.y; acc[1][2] += a.y * b.z; acc[1][3] += a.y * b.w;
            acc[2][0] += a.z * b.x; acc[2][1] += a.z * b.y; acc[2][2] += a.z * b.z; acc[2][3] += a.z * b.w;
            acc[3][0] += a.w * b.x; acc[3][1] += a.w * b.y; acc[3][2] += a.w * b.z; acc[3][3] += a.w * b.w;
        }
        __syncthreads();
    }
    float* S = g_s + (size_t)z * N_TOK * SUBN;
#pragma unroll
    for (int i = 0; i < 4; i++) {
        int row = bm + (ty << 2) + i;
        float4 o = { acc[i][0], acc[i][1], acc[i][2], acc[i][3] };
        *(float4*)(S + (size_t)row * SUBN + bn + (tx << 2)) = o;
    }
}

// ---------------- two-level top-k + softmax ----------------
__global__ void __launch_bounds__(64) topk_kernel()
{
    const int b = blockIdx.x;
    const int t = b >> 2, h = b & 3;
    const int w = threadIdx.x >> 5;          // half index (warp)
    const int lane = threadIdx.x & 31;

    __shared__ float sts[2][32];
    __shared__ int   sti[2][32];
    __shared__ float cv[128];
    __shared__ int   ci[128];

    // phase 1: each warp extracts sorted top-32 of its 512-score row
    {
        const float* row = g_s + ((size_t)(h * 2 + w) * N_TOK + t) * SUBN;
        float v[16];
#pragma unroll
        for (int c = 0; c < 16; c++) v[c] = row[lane + 32 * c];
        float myv = 0.f; int myi = 0;
        for (int it = 0; it < 32; it++) {
            float lm = neg_inf(); int lc2 = 0;
#pragma unroll
            for (int c = 0; c < 16; c++) if (v[c] > lm) { lm = v[c]; lc2 = c; }
            float bv = lm; int bi = lane + 32 * lc2;   // original index, ties -> lower idx
#pragma unroll
            for (int o = 16; o > 0; o >>= 1) {
                float ov = __shfl_xor_sync(0xffffffffu, bv, o);
                int   oi = __shfl_xor_sync(0xffffffffu, bi, o);
                if (ov > bv || (ov == bv && oi < bi)) { bv = ov; bi = oi; }
            }
            if (lane == it) { myv = bv; myi = bi; }
            if (lane == (bi & 31)) {
                int cc = bi >> 5;
#pragma unroll
                for (int c = 0; c < 16; c++) if (c == cc) v[c] = neg_inf();
            }
        }
        sts[w][lane] = myv; sti[w][lane] = myi;
    }
    __syncthreads();

    // phase 2: warp 0 combines pair sums (pruned to 119 candidates), top-32, softmax
    if (w == 0) {
#pragma unroll
        for (int c = 0; c < 4; c++) cv[lane + 32 * c] = neg_inf();
        __syncwarp();
        {
            const int jm = c_jm[lane], base = c_base[lane];
            const float a = sts[0][lane];
            const int  ia = sti[0][lane];
            for (int j = 0; j < jm; j++) {
                cv[base + j] = a + sts[1][j];
                ci[base + j] = ia * SUBN + sti[1][j];
            }
        }
        __syncwarp();
        float v[4];
#pragma unroll
        for (int c = 0; c < 4; c++) v[c] = cv[lane + 32 * c];
        float myv = 0.f; int mys = 0;
        for (int it = 0; it < 32; it++) {
            float lm = neg_inf(); int lc2 = 0;
#pragma unroll
            for (int c = 0; c < 4; c++) if (v[c] > lm) { lm = v[c]; lc2 = c; }
            float bv = lm; int bi = lane + 32 * lc2;   // slot order == lexicographic (i,j)
#pragma unroll
            for (int o = 16; o > 0; o >>= 1) {
                float ov = __shfl_xor_sync(0xffffffffu, bv, o);
                int   oi = __shfl_xor_sync(0xffffffffu, bi, o);
                if (ov > bv || (ov == bv && oi < bi)) { bv = ov; bi = oi; }
            }
            if (lane == it) { myv = bv; mys = bi; }
            if (lane == (bi & 31)) {
                int cc = bi >> 5;
#pragma unroll
                for (int c = 0; c < 4; c++) if (c == cc) v[c] = neg_inf();
            }
        }
        const float mx = __shfl_sync(0xffffffffu, myv, 0);
        float e = expf(myv - mx);
        float sum = e;
#pragma unroll
        for (int o = 16; o > 0; o >>= 1) sum += __shfl_xor_sync(0xffffffffu, sum, o);
        const size_t oo = (size_t)t * (HEADS * KNN) + h * KNN + lane;
        g_idx[oo] = ci[mys];
        g_w[oo]   = e / sum;
    }
}

// ---------------- weighted gather from values table ----------------
__global__ void __launch_bounds__(128) gather_kernel(const float* __restrict__ values)
{
    const int t = blockIdx.x;
    const int tid = threadIdx.x;
    __shared__ int   sidx[128];
    __shared__ float sw[128];
    sidx[tid] = g_idx[(size_t)t * 128 + tid];
    sw[tid]   = g_w[(size_t)t * 128 + tid];
    __syncthreads();

    const int col = tid << 2;
    float4 acc = {0.f, 0.f, 0.f, 0.f};
#pragma unroll 4
    for (int k = 0; k < 128; k++) {
        const float4 vv = *(const float4*)(values + (size_t)sidx[k] * HDIM + col);
        const float wk = sw[k];
        acc.x += wk * vv.x; acc.y += wk * vv.y;
        acc.z += wk * vv.z; acc.w += wk * vv.w;
    }
    *(float4*)(g_partial + (size_t)t * HDIM + col) = acc;
}

// ---------------- deterministic reduce over sequence ----------------
__global__ void __launch_bounds__(512) reduce_kernel(float* __restrict__ out)
{
    const int e = blockIdx.x * 512 + threadIdx.x;   // 0..16383
    const int bb = e >> 9, c = e & 511;
    float s = 0.f;
#pragma unroll 8
    for (int l = 0; l < 64; l++)
        s += g_partial[(size_t)((bb << 6) + l) * HDIM + c];
    out[e] = s;
}

// ---------------- launch ----------------
extern "C" void kernel_launch(void* const* d_in, const int* in_sizes, int n_in,
                              void* d_out, int out_size)
{
    (void)in_sizes; (void)n_in; (void)out_size;
    const float* x        = (const float*)d_in[0];
    const float* w1       = (const float*)d_in[1];
    const float* b1       = (const float*)d_in[2];
    const float* w2       = (const float*)d_in[3];
    const float* b2       = (const float*)d_in[4];
    const float* bn_gamma = (const float*)d_in[5];
    const float* bn_beta  = (const float*)d_in[6];
    const float* keys     = (const float*)d_in[7];
    const float* values   = (const float*)d_in[8];
    float* out = (float*)d_out;

    float *d_h, *d_q;
    cudaGetSymbolAddress((void**)&d_h, g_h);
    cudaGetSymbolAddress((void**)&d_q, g_q);

    // 1) h = relu(x @ w1^T + b1)   [2048 x 256]
    gemm_bias<true><<<dim3(N_TOK / 64, C1 / 64), 256>>>(x, w1, b1, d_h, N_TOK, C1, HDIM);
    // 2) q = h @ w2^T + b2         [2048 x 1024]
    gemm_bias<false><<<dim3(N_TOK / 64, D2 / 64), 256>>>(d_h, w2, b2, d_q, N_TOK, D2, C1);
    // 3) BN stats
    bn_partial<<<128, 256>>>();
    bn_finalize<<<1, 256>>>(bn_gamma, bn_beta);
    // 4) scores (fused normalize) [8][2048][512]
    score_gemm<<<dim3(N_TOK / 64, SUBN / 64, 8), 256>>>(keys);
    // 5) two-level top-k + softmax
    topk_kernel<<<N_TOK * HEADS, 64>>>();
    // 6) weighted gather
    gather_kernel<<<N_TOK, 128>>>(values);
    // 7) sum over sequence
    reduce_kernel<<<32, 512>>>(out);
}